// round 15
// baseline (speedup 1.0000x reference)
#include <cuda_runtime.h>
#include <cuda_bf16.h>
#include <math.h>
#include <cstdint>

#define Bb 2
#define Nn 160
#define Cc 256
#define Hh 8
#define Dd 32
#define ROWS (Bb*Nn*Nn)   // 51200
#define GK 256            // inner K of all GEMMs

typedef unsigned long long ull;

// ---------------- scratch (__device__ globals; no allocation allowed) ----------------
__device__ __nv_bfloat16 g_qkvh[(size_t)ROWS*768];
__device__ __nv_bfloat16 g_qkvl[(size_t)ROWS*768];
__device__ float g_proj[(size_t)ROWS*Cc];
__device__ float g_x1[(size_t)ROWS*Cc];
__device__ float g_mapT[(size_t)Bb*Nn*Nn];
__device__ __nv_bfloat16 g_Ah[(size_t)ROWS*GK];
__device__ __nv_bfloat16 g_Al[(size_t)ROWS*GK];
__device__ __nv_bfloat16 g_Brq[(size_t)768*2*GK];
__device__ __nv_bfloat16 g_Bro[(size_t)256*2*GK];
__device__ __nv_bfloat16 g_Bcq[(size_t)768*2*GK];
__device__ __nv_bfloat16 g_Bco[(size_t)256*2*GK];

__device__ __forceinline__ uint32_t smem_u32(const void* p) {
    uint32_t a;
    asm("{ .reg .u64 t; cvta.to.shared.u64 t, %1; cvt.u32.u64 %0, t; }" : "=r"(a) : "l"(p));
    return a;
}
#define CP16(d, s) asm volatile("cp.async.cg.shared.global [%0], [%1], 16;" :: "r"(d), "l"(s))
#define CP_COMMIT  asm volatile("cp.async.commit_group;" ::: "memory")

__device__ __forceinline__ uint32_t bpack(__nv_bfloat16 a, __nv_bfloat16 b) {
    __nv_bfloat162 t(a, b);
    return *reinterpret_cast<uint32_t*>(&t);
}
__device__ __forceinline__ void split2(float x, float y, uint32_t& hi, uint32_t& lo) {
    __nv_bfloat16 hx = __float2bfloat16(x), hy = __float2bfloat16(y);
    hi = bpack(hx, hy);
    lo = bpack(__float2bfloat16(x - __bfloat162float(hx)),
               __float2bfloat16(y - __bfloat162float(hy)));
}

#define MMA16816(d, a, b) \
    asm volatile("mma.sync.aligned.m16n8k16.row.col.f32.bf16.bf16.f32 " \
                 "{%0,%1,%2,%3}, {%4,%5,%6,%7}, {%8,%9}, {%0,%1,%2,%3};" \
                 : "+f"((d)[0]), "+f"((d)[1]), "+f"((d)[2]), "+f"((d)[3]) \
                 : "r"((a)[0]), "r"((a)[1]), "r"((a)[2]), "r"((a)[3]), \
                   "r"((b)[0]), "r"((b)[1]))

#define LDSM_X4(r, addr) \
    asm volatile("ldmatrix.sync.aligned.m8n8.x4.shared.b16 {%0,%1,%2,%3}, [%4];" \
                 : "=r"((r)[0]), "=r"((r)[1]), "=r"((r)[2]), "=r"((r)[3]) : "r"(addr))
#define LDSM_X2(r0, r1, addr) \
    asm volatile("ldmatrix.sync.aligned.m8n8.x2.shared.b16 {%0,%1}, [%2];" \
                 : "=r"(r0), "=r"(r1) : "r"(addr))
#define LDSM_X4T(r, addr) \
    asm volatile("ldmatrix.sync.aligned.m8n8.x4.trans.shared.b16 {%0,%1,%2,%3}, [%4];" \
                 : "=r"((r)[0]), "=r"((r)[1]), "=r"((r)[2]), "=r"((r)[3]) : "r"(addr))

// ---------------- map transpose: mapT[b,i,j] = map[b,j,i] ----------------
__global__ __launch_bounds__(256) void tmap_kernel(const float* __restrict__ m,
                                                   float* __restrict__ mt) {
    __shared__ float tile[32][33];
    const int b = blockIdx.z;
    const int x = blockIdx.x * 32 + threadIdx.x;
    const int ty = threadIdx.y;
#pragma unroll
    for (int dy = 0; dy < 32; dy += 8) {
        int y = blockIdx.y * 32 + ty + dy;
        tile[ty + dy][threadIdx.x] = m[(size_t)b * Nn * Nn + (size_t)y * Nn + x];
    }
    __syncthreads();
    const int xo = blockIdx.y * 32 + threadIdx.x;
#pragma unroll
    for (int dy = 0; dy < 32; dy += 8) {
        int yo = blockIdx.x * 32 + ty + dy;
        mt[(size_t)b * Nn * Nn + (size_t)yo * Nn + xo] = tile[threadIdx.x][ty + dy];
    }
}

// ---------------- fused weight split ----------------
__device__ __forceinline__ void wsplit_one(const float* W, __nv_bfloat16* Bt, int Nc, int idx) {
    int k = idx / Nc, n = idx % Nc;
    float x = W[idx];
    __nv_bfloat16 h = __float2bfloat16(x);
    Bt[(size_t)n * (2 * GK) + k]      = h;
    Bt[(size_t)n * (2 * GK) + GK + k] = __float2bfloat16(x - __bfloat162float(h));
}
__global__ __launch_bounds__(256) void splitW(const float* __restrict__ wrq,
                                              const float* __restrict__ wro,
                                              const float* __restrict__ wcq,
                                              const float* __restrict__ wco,
                                              __nv_bfloat16* __restrict__ brq,
                                              __nv_bfloat16* __restrict__ bro,
                                              __nv_bfloat16* __restrict__ bcq,
                                              __nv_bfloat16* __restrict__ bco) {
    int idx = blockIdx.x * blockDim.x + threadIdx.x;
    const int NQ = GK * 768, NO = GK * 256;
    if (idx < NQ) { wsplit_one(wrq, brq, 768, idx); return; }
    idx -= NQ;
    if (idx < NQ) { wsplit_one(wcq, bcq, 768, idx); return; }
    idx -= NQ;
    if (idx < NO) { wsplit_one(wro, bro, 256, idx); return; }
    idx -= NO;
    if (idx < NO) { wsplit_one(wco, bco, 256, idx); }
}

// ---------------- splitA: fp32 -> bf16 hi/lo ----------------
__global__ __launch_bounds__(256) void splitA(const float4* __restrict__ X,
                                              __nv_bfloat16* __restrict__ Ah,
                                              __nv_bfloat16* __restrict__ Al, int n4) {
    int i = blockIdx.x * blockDim.x + threadIdx.x;
    if (i >= n4) return;
    float4 x = X[i];
    uint32_t h0, l0, h1, l1;
    split2(x.x, x.y, h0, l0);
    split2(x.z, x.w, h1, l1);
    reinterpret_cast<uint32_t*>(Ah)[i * 2 + 0] = h0;
    reinterpret_cast<uint32_t*>(Ah)[i * 2 + 1] = h1;
    reinterpret_cast<uint32_t*>(Al)[i * 2 + 0] = l0;
    reinterpret_cast<uint32_t*>(Al)[i * 2 + 1] = l1;
}

// ---------------- bf16 mma.sync GEMM, BM=128 BN=64, 3 CTAs/SM ----------------
#define SSTR 40
#define ATILE (128 * SSTR)                       // per A tile (hi or lo)
#define BTILE (64 * SSTR)                        // per B tile (hi or lo)
#define STAGE_ELEMS (2 * ATILE + 2 * BTILE)      // 15360 bf16
#define NCHUNK (GK / 32)
#define GSMEM (2 * STAGE_ELEMS * 2)              // 61440 B

__global__ __launch_bounds__(256, 3) void gemm_mma(const __nv_bfloat16* __restrict__ Ah,
                                                const __nv_bfloat16* __restrict__ Al,
                                                const __nv_bfloat16* __restrict__ Bt,
                                                float* __restrict__ Cf,
                                                __nv_bfloat16* __restrict__ Ch,
                                                __nv_bfloat16* __restrict__ Cl, int Nc) {
    extern __shared__ __nv_bfloat16 gsm[];
    // stage layout: [Ah 128x40][Al 128x40][Bh 64x40][Bl 64x40]

    const int tid = threadIdx.x;
    const int wid = tid >> 5, l = tid & 31;
    const int wm = (wid & 3) * 32;
    const int wn = (wid >> 2) * 32;
    const int bm = blockIdx.y * 128, bn = blockIdx.x * 64;

    float acc[2][4][4];
#pragma unroll
    for (int mt = 0; mt < 2; mt++)
#pragma unroll
        for (int nt = 0; nt < 4; nt++)
#pragma unroll
            for (int r = 0; r < 4; r++) acc[mt][nt][r] = 0.f;

    auto load_chunk = [&](int c, int st) {
        const int k0 = c * 32;
        __nv_bfloat16* base = gsm + st * STAGE_ELEMS;
        // A: 128 rows x 4 segs (hi then lo) = 512 CP16 each -> 2 rounds of 256
#pragma unroll
        for (int w = 0; w < 2; w++) {
            int idx = tid + w * 256;
            int row = idx >> 2, seg = (idx & 3) * 8;
            uint32_t soff = (uint32_t)(row * SSTR + seg);
            CP16(smem_u32(base + soff),
                 Ah + (size_t)(bm + row) * GK + k0 + seg);
            CP16(smem_u32(base + ATILE + soff),
                 Al + (size_t)(bm + row) * GK + k0 + seg);
        }
        // B: 64 rows x 4 segs = 256 CP16 each (hi, lo) -> 1 round each
        {
            int row = tid >> 2, seg = (tid & 3) * 8;
            uint32_t soff = (uint32_t)(row * SSTR + seg);
            CP16(smem_u32(base + 2 * ATILE + soff),
                 Bt + (size_t)(bn + row) * (2 * GK) + k0 + seg);
            CP16(smem_u32(base + 2 * ATILE + BTILE + soff),
                 Bt + (size_t)(bn + row) * (2 * GK) + GK + k0 + seg);
        }
        CP_COMMIT;
    };

    load_chunk(0, 0);

    int st = 0;
    for (int c = 0; c < NCHUNK; c++) {
        asm volatile("cp.async.wait_group 0;" ::: "memory");
        __syncthreads();
        if (c + 1 < NCHUNK) load_chunk(c + 1, st ^ 1);

        const __nv_bfloat16* base = gsm + st * STAGE_ELEMS;
        const uint32_t aHb = smem_u32(base);
        const uint32_t aLb = smem_u32(base + ATILE);
        const uint32_t bHb = smem_u32(base + 2 * ATILE);
        const uint32_t bLb = smem_u32(base + 2 * ATILE + BTILE);

#pragma unroll
        for (int ks = 0; ks < 32; ks += 16) {
            uint32_t ah[2][4], al[2][4], bh[4][2], bl[4][2];
            uint32_t aoff[2], boff[2];
#pragma unroll
            for (int mt = 0; mt < 2; mt++)
                aoff[mt] = (((wm + mt * 16 + (l & 15)) * SSTR) + ks + ((l >> 4) << 3)) * 2;
#pragma unroll
            for (int p = 0; p < 2; p++)
                boff[p] = (((wn + p * 16 + (l & 7) + ((l >> 4) << 3)) * SSTR) +
                           ks + (((l >> 3) & 1) << 3)) * 2;

#pragma unroll
            for (int mt = 0; mt < 2; mt++) LDSM_X4(ah[mt], aHb + aoff[mt]);
#pragma unroll
            for (int p = 0; p < 2; p++)
                asm volatile("ldmatrix.sync.aligned.m8n8.x4.shared.b16 {%0,%1,%2,%3}, [%4];"
                             : "=r"(bh[p * 2][0]), "=r"(bh[p * 2][1]),
                               "=r"(bh[p * 2 + 1][0]), "=r"(bh[p * 2 + 1][1])
                             : "r"(bHb + boff[p]));
#pragma unroll
            for (int mt = 0; mt < 2; mt++)
#pragma unroll
                for (int nt = 0; nt < 4; nt++) MMA16816(acc[mt][nt], ah[mt], bh[nt]);

#pragma unroll
            for (int p = 0; p < 2; p++)
                asm volatile("ldmatrix.sync.aligned.m8n8.x4.shared.b16 {%0,%1,%2,%3}, [%4];"
                             : "=r"(bl[p * 2][0]), "=r"(bl[p * 2][1]),
                               "=r"(bl[p * 2 + 1][0]), "=r"(bl[p * 2 + 1][1])
                             : "r"(bLb + boff[p]));
#pragma unroll
            for (int mt = 0; mt < 2; mt++)
#pragma unroll
                for (int nt = 0; nt < 4; nt++) MMA16816(acc[mt][nt], ah[mt], bl[nt]);

#pragma unroll
            for (int mt = 0; mt < 2; mt++) LDSM_X4(al[mt], aLb + aoff[mt]);
#pragma unroll
            for (int mt = 0; mt < 2; mt++)
#pragma unroll
                for (int nt = 0; nt < 4; nt++) MMA16816(acc[mt][nt], al[mt], bh[nt]);
        }
        st ^= 1;
    }

    if (Cf) {
#pragma unroll
        for (int mt = 0; mt < 2; mt++) {
            const int row = bm + wm + mt * 16 + (l >> 2);
#pragma unroll
            for (int nt = 0; nt < 4; nt++) {
                const int col = bn + wn + nt * 8 + (l & 3) * 2;
                *reinterpret_cast<float2*>(Cf + (size_t)row * Nc + col) =
                    make_float2(acc[mt][nt][0], acc[mt][nt][1]);
                *reinterpret_cast<float2*>(Cf + (size_t)(row + 8) * Nc + col) =
                    make_float2(acc[mt][nt][2], acc[mt][nt][3]);
            }
        }
    } else {
#pragma unroll
        for (int mt = 0; mt < 2; mt++) {
            const int row = bm + wm + mt * 16 + (l >> 2);
#pragma unroll
            for (int nt = 0; nt < 4; nt++) {
                const int col = bn + wn + nt * 8 + (l & 3) * 2;
                uint32_t h0, l0, h1, l1;
                split2(acc[mt][nt][0], acc[mt][nt][1], h0, l0);
                split2(acc[mt][nt][2], acc[mt][nt][3], h1, l1);
                *reinterpret_cast<uint32_t*>(Ch + (size_t)row * Nc + col)       = h0;
                *reinterpret_cast<uint32_t*>(Cl + (size_t)row * Nc + col)       = l0;
                *reinterpret_cast<uint32_t*>(Ch + (size_t)(row + 8) * Nc + col) = h1;
                *reinterpret_cast<uint32_t*>(Cl + (size_t)(row + 8) * Nc + col) = l1;
            }
        }
    }
}

// ---------------- tensor-core attention: 2 heads per block ----------------
#define ASTR 40
#define AT_TILE (Nn * ASTR)
#define MSTR 168
#define MAP_SM (Nn * MSTR)
#define ATTN_SMEM (MAP_SM * 4 + 2 * 4 * AT_TILE * 2)

__global__ __launch_bounds__(320, 1) void attn_mma(const __nv_bfloat16* __restrict__ qkvh,
                                                   const __nv_bfloat16* __restrict__ qkvl,
                                                   const float* __restrict__ mapsrc,
                                                   const float* __restrict__ bw,
                                                   const float* __restrict__ bb,
                                                   __nv_bfloat16* __restrict__ Ah,
                                                   __nv_bfloat16* __restrict__ Al) {
    extern __shared__ char asmem[];
    float* mapS = reinterpret_cast<float*>(asmem);
    __nv_bfloat16* tiles = reinterpret_cast<__nv_bfloat16*>(asmem + MAP_SM * 4);
    auto sKh = [&](int st) { return tiles + st * 4 * AT_TILE + 0 * AT_TILE; };
    auto sKl = [&](int st) { return tiles + st * 4 * AT_TILE + 1 * AT_TILE; };
    auto sVh = [&](int st) { return tiles + st * 4 * AT_TILE + 2 * AT_TILE; };
    auto sVl = [&](int st) { return tiles + st * 4 * AT_TILE + 3 * AT_TILE; };

    const int m = blockIdx.x, b = blockIdx.y;
    const int hbase = blockIdx.z * 2;
    const int tid = threadIdx.x, wid = tid >> 5, l = tid & 31;
    const size_t rowbase = ((size_t)b * Nn + m) * Nn;
    const float scale = 0.17677669529663687f;

    for (int idx = tid; idx < Nn * 40; idx += 320) {
        int row = idx / 40, c4 = idx % 40;
        CP16(smem_u32(mapS + row * MSTR + c4 * 4),
             mapsrc + (size_t)b * Nn * Nn + (size_t)row * Nn + c4 * 4);
    }
    CP_COMMIT;

    auto load_kv = [&](int h, int st) {
        for (int idx = tid; idx < Nn * 4; idx += 320) {
            int row = idx >> 2, seg = (idx & 3) * 8;
            size_t gro = (rowbase + row) * 768 + 256 + h * Dd;
            uint32_t so = (uint32_t)(row * ASTR + seg);
            CP16(smem_u32(sKh(st) + so), qkvh + gro + seg);
            CP16(smem_u32(sKl(st) + so), qkvl + gro + seg);
            CP16(smem_u32(sVh(st) + so), qkvh + gro + 256 + seg);
            CP16(smem_u32(sVl(st) + so), qkvl + gro + 256 + seg);
        }
        CP_COMMIT;
    };

    load_kv(hbase, 0);

    const int q0 = wid * 16;
    const int r0 = q0 + (l >> 2), r1 = r0 + 8;
    const int cpair = (l & 3) * 2;

    for (int e = 0; e < 2; e++) {
        const int h = hbase + e, st = e;
        if (e == 0) {
            load_kv(hbase + 1, 1);
            asm volatile("cp.async.wait_group 1;" ::: "memory");
        } else {
            asm volatile("cp.async.wait_group 0;" ::: "memory");
        }
        __syncthreads();

        const float wv = bw[h], bv = bb[h];

        uint32_t qh[2][4], ql[2][4];
        {
            const size_t g0 = (rowbase + r0) * 768 + h * Dd;
            const size_t g1 = (rowbase + r1) * 768 + h * Dd;
#pragma unroll
            for (int kc = 0; kc < 2; kc++) {
                int col = kc * 16 + cpair;
                qh[kc][0] = *reinterpret_cast<const uint32_t*>(qkvh + g0 + col);
                qh[kc][1] = *reinterpret_cast<const uint32_t*>(qkvh + g1 + col);
                qh[kc][2] = *reinterpret_cast<const uint32_t*>(qkvh + g0 + col + 8);
                qh[kc][3] = *reinterpret_cast<const uint32_t*>(qkvh + g1 + col + 8);
                ql[kc][0] = *reinterpret_cast<const uint32_t*>(qkvl + g0 + col);
                ql[kc][1] = *reinterpret_cast<const uint32_t*>(qkvl + g1 + col);
                ql[kc][2] = *reinterpret_cast<const uint32_t*>(qkvl + g0 + col + 8);
                ql[kc][3] = *reinterpret_cast<const uint32_t*>(qkvl + g1 + col + 8);
            }
        }

        float S[20][4];
#pragma unroll
        for (int nt = 0; nt < 20; nt++)
#pragma unroll
            for (int r = 0; r < 4; r++) S[nt][r] = 0.f;

        const uint32_t kHb = smem_u32(sKh(st)), kLb = smem_u32(sKl(st));
#pragma unroll
        for (int nt = 0; nt < 20; nt++) {
#pragma unroll
            for (int kc = 0; kc < 2; kc++) {
                uint32_t off = (uint32_t)((nt * 8 + (l & 7)) * ASTR) * 2 +
                               (((l >> 3) & 1) << 4) + kc * 32;
                uint32_t bh[2], bl2[2];
                LDSM_X2(bh[0], bh[1], kHb + off);
                LDSM_X2(bl2[0], bl2[1], kLb + off);
                MMA16816(S[nt], qh[kc], bh);
                MMA16816(S[nt], qh[kc], bl2);
                MMA16816(S[nt], ql[kc], bh);
            }
        }

#pragma unroll
        for (int nt = 0; nt < 20; nt++) {
            int j0 = nt * 8 + cpair;
            S[nt][0] = S[nt][0] * scale + mapS[r0 * MSTR + j0]     * wv + bv;
            S[nt][1] = S[nt][1] * scale + mapS[r0 * MSTR + j0 + 1] * wv + bv;
            S[nt][2] = S[nt][2] * scale + mapS[r1 * MSTR + j0]     * wv + bv;
            S[nt][3] = S[nt][3] * scale + mapS[r1 * MSTR + j0 + 1] * wv + bv;
        }

        float m0 = -INFINITY, m1 = -INFINITY;
#pragma unroll
        for (int nt = 0; nt < 20; nt++) {
            m0 = fmaxf(m0, fmaxf(S[nt][0], S[nt][1]));
            m1 = fmaxf(m1, fmaxf(S[nt][2], S[nt][3]));
        }
        m0 = fmaxf(m0, __shfl_xor_sync(0xffffffffu, m0, 1));
        m0 = fmaxf(m0, __shfl_xor_sync(0xffffffffu, m0, 2));
        m1 = fmaxf(m1, __shfl_xor_sync(0xffffffffu, m1, 1));
        m1 = fmaxf(m1, __shfl_xor_sync(0xffffffffu, m1, 2));

        float l0 = 0.f, l1 = 0.f;
#pragma unroll
        for (int nt = 0; nt < 20; nt++) {
            S[nt][0] = __expf(S[nt][0] - m0); l0 += S[nt][0];
            S[nt][1] = __expf(S[nt][1] - m0); l0 += S[nt][1];
            S[nt][2] = __expf(S[nt][2] - m1); l1 += S[nt][2];
            S[nt][3] = __expf(S[nt][3] - m1); l1 += S[nt][3];
        }
        l0 += __shfl_xor_sync(0xffffffffu, l0, 1);
        l0 += __shfl_xor_sync(0xffffffffu, l0, 2);
        l1 += __shfl_xor_sync(0xffffffffu, l1, 1);
        l1 += __shfl_xor_sync(0xffffffffu, l1, 2);

        float O[4][4];
#pragma unroll
        for (int nt = 0; nt < 4; nt++)
#pragma unroll
            for (int r = 0; r < 4; r++) O[nt][r] = 0.f;

        const uint32_t vHb = smem_u32(sVh(st)), vLb = smem_u32(sVl(st));
#pragma unroll
        for (int kc = 0; kc < 10; kc++) {
            uint32_t aPh[4], aPl[4];
            split2(S[kc * 2][0],     S[kc * 2][1],     aPh[0], aPl[0]);
            split2(S[kc * 2][2],     S[kc * 2][3],     aPh[1], aPl[1]);
            split2(S[kc * 2 + 1][0], S[kc * 2 + 1][1], aPh[2], aPl[2]);
            split2(S[kc * 2 + 1][2], S[kc * 2 + 1][3], aPh[3], aPl[3]);

            uint32_t bvh[4][2], bvl[4][2];
#pragma unroll
            for (int dp = 0; dp < 2; dp++) {
                uint32_t off = (uint32_t)((kc * 16 + (l & 15)) * ASTR) * 2 +
                               ((l >> 4) << 4) + dp * 32;
                uint32_t rh[4], rl[4];
                LDSM_X4T(rh, vHb + off);
                LDSM_X4T(rl, vLb + off);
                bvh[dp * 2][0] = rh[0]; bvh[dp * 2][1] = rh[1];
                bvh[dp * 2 + 1][0] = rh[2]; bvh[dp * 2 + 1][1] = rh[3];
                bvl[dp * 2][0] = rl[0]; bvl[dp * 2][1] = rl[1];
                bvl[dp * 2 + 1][0] = rl[2]; bvl[dp * 2 + 1][1] = rl[3];
            }
#pragma unroll
            for (int nt = 0; nt < 4; nt++) {
                MMA16816(O[nt], aPh, bvh[nt]);
                MMA16816(O[nt], aPh, bvl[nt]);
                MMA16816(O[nt], aPl, bvh[nt]);
            }
        }

        const float inv0 = 1.f / l0, inv1 = 1.f / l1;
#pragma unroll
        for (int nt = 0; nt < 4; nt++) {
            int col = h * Dd + nt * 8 + cpair;
            uint32_t h0v, l0v, h1v, l1v;
            split2(O[nt][0] * inv0, O[nt][1] * inv0, h0v, l0v);
            split2(O[nt][2] * inv1, O[nt][3] * inv1, h1v, l1v);
            *reinterpret_cast<uint32_t*>(Ah + (rowbase + r0) * GK + col) = h0v;
            *reinterpret_cast<uint32_t*>(Al + (rowbase + r0) * GK + col) = l0v;
            *reinterpret_cast<uint32_t*>(Ah + (rowbase + r1) * GK + col) = h1v;
            *reinterpret_cast<uint32_t*>(Al + (rowbase + r1) * GK + col) = l1v;
        }
        if (e == 0) __syncthreads();
    }
}

// ---------------- Residual + LayerNorm: warp-per-row, no smem/syncs ----------------
__global__ __launch_bounds__(256) void ln_kernel(const float* __restrict__ xin,
                                                const float* __restrict__ proj,
                                                const float* __restrict__ g,
                                                const float* __restrict__ bt,
                                                float* __restrict__ out,
                                                __nv_bfloat16* __restrict__ Ah,
                                                __nv_bfloat16* __restrict__ Al) {
    const int wid = threadIdx.x >> 5, l = threadIdx.x & 31;
    const int r = blockIdx.x * 8 + wid;

    const float4* x4 = reinterpret_cast<const float4*>(xin + (size_t)r * Cc);
    const float4* p4 = reinterpret_cast<const float4*>(proj + (size_t)r * Cc);
    float4 v[2];
    float s = 0.f, s2 = 0.f;
#pragma unroll
    for (int k = 0; k < 2; k++) {
        float4 a = x4[l + k * 32], p = p4[l + k * 32];
        v[k] = make_float4(a.x + p.x, a.y + p.y, a.z + p.z, a.w + p.w);
        s  += v[k].x + v[k].y + v[k].z + v[k].w;
        s2 += v[k].x * v[k].x + v[k].y * v[k].y + v[k].z * v[k].z + v[k].w * v[k].w;
    }
#pragma unroll
    for (int o = 16; o > 0; o >>= 1) {
        s  += __shfl_xor_sync(0xffffffffu, s, o);
        s2 += __shfl_xor_sync(0xffffffffu, s2, o);
    }
    const float mean = s * (1.f / Cc);
    const float var  = s2 * (1.f / Cc) - mean * mean;
    const float rs   = rsqrtf(var + 1e-5f);

    const int bidx = r / (Nn * Nn);
    const int rem  = r % (Nn * Nn);
    const int mm   = rem / Nn;
    const int ii   = rem % Nn;
    const size_t rt = ((size_t)bidx * Nn + ii) * Nn + mm;

    const float4* g4 = reinterpret_cast<const float4*>(g);
    const float4* b4 = reinterpret_cast<const float4*>(bt);
    float4* o4 = reinterpret_cast<float4*>(out + rt * Cc);
#pragma unroll
    for (int k = 0; k < 2; k++) {
        float4 gg = g4[l + k * 32], bb2 = b4[l + k * 32];
        float4 y;
        y.x = (v[k].x - mean) * rs * gg.x + bb2.x;
        y.y = (v[k].y - mean) * rs * gg.y + bb2.y;
        y.z = (v[k].z - mean) * rs * gg.z + bb2.z;
        y.w = (v[k].w - mean) * rs * gg.w + bb2.w;
        o4[l + k * 32] = y;
        if (Ah) {
            uint32_t h0, l0, h1, l1;
            split2(y.x, y.y, h0, l0);
            split2(y.z, y.w, h1, l1);
            *reinterpret_cast<uint2*>(Ah + rt * GK + (l + k * 32) * 4) = make_uint2(h0, h1);
            *reinterpret_cast<uint2*>(Al + rt * GK + (l + k * 32) * 4) = make_uint2(l0, l1);
        }
    }
}

extern "C" void kernel_launch(void* const* d_in, const int* in_sizes, int n_in,
                              void* d_out, int out_size) {
    const float* pair      = (const float*)d_in[0];
    const float* bulk      = (const float*)d_in[1];
    const float* row_qkv_w = (const float*)d_in[2];
    const float* row_out_w = (const float*)d_in[3];
    const float* row_ln_g  = (const float*)d_in[4];
    const float* row_ln_b  = (const float*)d_in[5];
    const float* row_bw    = (const float*)d_in[6];
    const float* row_bb    = (const float*)d_in[7];
    const float* col_qkv_w = (const float*)d_in[8];
    const float* col_out_w = (const float*)d_in[9];
    const float* col_ln_g  = (const float*)d_in[10];
    const float* col_ln_b  = (const float*)d_in[11];
    const float* col_bw    = (const float*)d_in[12];
    const float* col_bb    = (const float*)d_in[13];
    float* out = (float*)d_out;

    float *proj, *x1, *mapT;
    __nv_bfloat16 *qkvh, *qkvl, *Ah, *Al, *Brq, *Bro, *Bcq, *Bco;
    cudaGetSymbolAddress((void**)&qkvh, g_qkvh);
    cudaGetSymbolAddress((void**)&qkvl, g_qkvl);
    cudaGetSymbolAddress((void**)&proj, g_proj);
    cudaGetSymbolAddress((void**)&x1,   g_x1);
    cudaGetSymbolAddress((void**)&mapT, g_mapT);
    cudaGetSymbolAddress((void**)&Ah,   g_Ah);
    cudaGetSymbolAddress((void**)&Al,   g_Al);
    cudaGetSymbolAddress((void**)&Brq,  g_Brq);
    cudaGetSymbolAddress((void**)&Bro,  g_Bro);
    cudaGetSymbolAddress((void**)&Bcq,  g_Bcq);
    cudaGetSymbolAddress((void**)&Bco,  g_Bco);

    cudaFuncSetAttribute(attn_mma, cudaFuncAttributeMaxDynamicSharedMemorySize, ATTN_SMEM);
    cudaFuncSetAttribute(gemm_mma, cudaFuncAttributeMaxDynamicSharedMemorySize, GSMEM);

    const int n4 = ROWS * GK / 4;
    const int gsplitA = (n4 + 255) / 256;
    const int nsplitW = 2 * GK * 768 + 2 * GK * 256;
    dim3 gq(768 / 64, ROWS / 128);
    dim3 gp(256 / 64, ROWS / 128);
    dim3 ga(Nn, Bb, Hh / 2);
    dim3 gt(Nn / 32, Nn / 32, Bb);

    // ---- prologue ----
    splitW<<<(nsplitW + 255) / 256, 256>>>(row_qkv_w, row_out_w, col_qkv_w, col_out_w,
                                           Brq, Bro, Bcq, Bco);
    tmap_kernel<<<gt, dim3(32, 8)>>>(bulk, mapT);
    splitA<<<gsplitA, 256>>>((const float4*)pair, Ah, Al, n4);

    // ---- pass 1 (row attention) ----
    gemm_mma<<<gq, 256, GSMEM>>>(Ah, Al, Brq, nullptr, qkvh, qkvl, 768);
    attn_mma<<<ga, 320, ATTN_SMEM>>>(qkvh, qkvl, bulk, row_bw, row_bb, Ah, Al);
    gemm_mma<<<gp, 256, GSMEM>>>(Ah, Al, Bro, proj, nullptr, nullptr, 256);
    ln_kernel<<<ROWS / 8, 256>>>(pair, proj, row_ln_g, row_ln_b, x1, Ah, Al);

    // ---- pass 2 (column attention) ----
    gemm_mma<<<gq, 256, GSMEM>>>(Ah, Al, Bcq, nullptr, qkvh, qkvl, 768);
    attn_mma<<<ga, 320, ATTN_SMEM>>>(qkvh, qkvl, mapT, col_bw, col_bb, Ah, Al);
    gemm_mma<<<gp, 256, GSMEM>>>(Ah, Al, Bco, proj, nullptr, nullptr, 256);
    ln_kernel<<<ROWS / 8, 256>>>(x1, proj, col_ln_g, col_ln_b, out, nullptr, nullptr);
}

// round 16
// speedup vs baseline: 1.0476x; 1.0476x over previous
#include <cuda_runtime.h>
#include <cuda_bf16.h>
#include <math.h>
#include <cstdint>

#define Bb 2
#define Nn 160
#define Cc 256
#define Hh 8
#define Dd 32
#define ROWS (Bb*Nn*Nn)   // 51200
#define GK 256            // inner K of all GEMMs

typedef unsigned long long ull;

// ---------------- scratch (__device__ globals; no allocation allowed) ----------------
__device__ __nv_bfloat16 g_qkvh[(size_t)ROWS*768];
__device__ __nv_bfloat16 g_qkvl[(size_t)ROWS*768];
__device__ float g_proj[(size_t)ROWS*Cc];
__device__ float g_x1[(size_t)ROWS*Cc];
__device__ float g_mapT[(size_t)Bb*Nn*Nn];
__device__ __nv_bfloat16 g_Ah[(size_t)ROWS*GK];
__device__ __nv_bfloat16 g_Al[(size_t)ROWS*GK];
__device__ __nv_bfloat16 g_Brq[(size_t)768*2*GK];
__device__ __nv_bfloat16 g_Bro[(size_t)256*2*GK];
__device__ __nv_bfloat16 g_Bcq[(size_t)768*2*GK];
__device__ __nv_bfloat16 g_Bco[(size_t)256*2*GK];

__device__ __forceinline__ uint32_t smem_u32(const void* p) {
    uint32_t a;
    asm("{ .reg .u64 t; cvta.to.shared.u64 t, %1; cvt.u32.u64 %0, t; }" : "=r"(a) : "l"(p));
    return a;
}
#define CP16(d, s) asm volatile("cp.async.cg.shared.global [%0], [%1], 16;" :: "r"(d), "l"(s))
#define CP_COMMIT  asm volatile("cp.async.commit_group;" ::: "memory")

__device__ __forceinline__ uint32_t bpack(__nv_bfloat16 a, __nv_bfloat16 b) {
    __nv_bfloat162 t(a, b);
    return *reinterpret_cast<uint32_t*>(&t);
}
__device__ __forceinline__ void split2(float x, float y, uint32_t& hi, uint32_t& lo) {
    __nv_bfloat16 hx = __float2bfloat16(x), hy = __float2bfloat16(y);
    hi = bpack(hx, hy);
    lo = bpack(__float2bfloat16(x - __bfloat162float(hx)),
               __float2bfloat16(y - __bfloat162float(hy)));
}

#define MMA16816(d, a, b) \
    asm volatile("mma.sync.aligned.m16n8k16.row.col.f32.bf16.bf16.f32 " \
                 "{%0,%1,%2,%3}, {%4,%5,%6,%7}, {%8,%9}, {%0,%1,%2,%3};" \
                 : "+f"((d)[0]), "+f"((d)[1]), "+f"((d)[2]), "+f"((d)[3]) \
                 : "r"((a)[0]), "r"((a)[1]), "r"((a)[2]), "r"((a)[3]), \
                   "r"((b)[0]), "r"((b)[1]))

#define LDSM_X4(r, addr) \
    asm volatile("ldmatrix.sync.aligned.m8n8.x4.shared.b16 {%0,%1,%2,%3}, [%4];" \
                 : "=r"((r)[0]), "=r"((r)[1]), "=r"((r)[2]), "=r"((r)[3]) : "r"(addr))
#define LDSM_X2(r0, r1, addr) \
    asm volatile("ldmatrix.sync.aligned.m8n8.x2.shared.b16 {%0,%1}, [%2];" \
                 : "=r"(r0), "=r"(r1) : "r"(addr))
#define LDSM_X4T(r, addr) \
    asm volatile("ldmatrix.sync.aligned.m8n8.x4.trans.shared.b16 {%0,%1,%2,%3}, [%4];" \
                 : "=r"((r)[0]), "=r"((r)[1]), "=r"((r)[2]), "=r"((r)[3]) : "r"(addr))

// ---------------- map transpose: mapT[b,i,j] = map[b,j,i] ----------------
__global__ __launch_bounds__(256) void tmap_kernel(const float* __restrict__ m,
                                                   float* __restrict__ mt) {
    __shared__ float tile[32][33];
    const int b = blockIdx.z;
    const int x = blockIdx.x * 32 + threadIdx.x;
    const int ty = threadIdx.y;
#pragma unroll
    for (int dy = 0; dy < 32; dy += 8) {
        int y = blockIdx.y * 32 + ty + dy;
        tile[ty + dy][threadIdx.x] = m[(size_t)b * Nn * Nn + (size_t)y * Nn + x];
    }
    __syncthreads();
    const int xo = blockIdx.y * 32 + threadIdx.x;
#pragma unroll
    for (int dy = 0; dy < 32; dy += 8) {
        int yo = blockIdx.x * 32 + ty + dy;
        mt[(size_t)b * Nn * Nn + (size_t)yo * Nn + xo] = tile[threadIdx.x][ty + dy];
    }
}

// ---------------- fused weight split ----------------
__device__ __forceinline__ void wsplit_one(const float* W, __nv_bfloat16* Bt, int Nc, int idx) {
    int k = idx / Nc, n = idx % Nc;
    float x = W[idx];
    __nv_bfloat16 h = __float2bfloat16(x);
    Bt[(size_t)n * (2 * GK) + k]      = h;
    Bt[(size_t)n * (2 * GK) + GK + k] = __float2bfloat16(x - __bfloat162float(h));
}
__global__ __launch_bounds__(256) void splitW(const float* __restrict__ wrq,
                                              const float* __restrict__ wro,
                                              const float* __restrict__ wcq,
                                              const float* __restrict__ wco,
                                              __nv_bfloat16* __restrict__ brq,
                                              __nv_bfloat16* __restrict__ bro,
                                              __nv_bfloat16* __restrict__ bcq,
                                              __nv_bfloat16* __restrict__ bco) {
    int idx = blockIdx.x * blockDim.x + threadIdx.x;
    const int NQ = GK * 768, NO = GK * 256;
    if (idx < NQ) { wsplit_one(wrq, brq, 768, idx); return; }
    idx -= NQ;
    if (idx < NQ) { wsplit_one(wcq, bcq, 768, idx); return; }
    idx -= NQ;
    if (idx < NO) { wsplit_one(wro, bro, 256, idx); return; }
    idx -= NO;
    if (idx < NO) { wsplit_one(wco, bco, 256, idx); }
}

// ---------------- splitA: fp32 -> bf16 hi/lo ----------------
__global__ __launch_bounds__(256) void splitA(const float4* __restrict__ X,
                                              __nv_bfloat16* __restrict__ Ah,
                                              __nv_bfloat16* __restrict__ Al, int n4) {
    int i = blockIdx.x * blockDim.x + threadIdx.x;
    if (i >= n4) return;
    float4 x = X[i];
    uint32_t h0, l0, h1, l1;
    split2(x.x, x.y, h0, l0);
    split2(x.z, x.w, h1, l1);
    reinterpret_cast<uint32_t*>(Ah)[i * 2 + 0] = h0;
    reinterpret_cast<uint32_t*>(Ah)[i * 2 + 1] = h1;
    reinterpret_cast<uint32_t*>(Al)[i * 2 + 0] = l0;
    reinterpret_cast<uint32_t*>(Al)[i * 2 + 1] = l1;
}

// ---------------- bf16 mma.sync GEMM, BM=128 BN=128 (round-14 config) ----------------
#define SSTR 40
#define GTILE (128 * SSTR)
#define NCHUNK (GK / 32)
#define GSMEM (2 * 4 * GTILE * 2)

__global__ __launch_bounds__(256, 2) void gemm_mma(const __nv_bfloat16* __restrict__ Ah,
                                                const __nv_bfloat16* __restrict__ Al,
                                                const __nv_bfloat16* __restrict__ Bt,
                                                float* __restrict__ Cf,
                                                __nv_bfloat16* __restrict__ Ch,
                                                __nv_bfloat16* __restrict__ Cl, int Nc) {
    extern __shared__ __nv_bfloat16 gsm[];

    const int tid = threadIdx.x;
    const int wid = tid >> 5, l = tid & 31;
    const int wm = (wid & 3) * 32;
    const int wn = (wid >> 2) * 64;
    const int bm = blockIdx.y * 128, bn = blockIdx.x * 128;

    float acc[2][8][4];
#pragma unroll
    for (int mt = 0; mt < 2; mt++)
#pragma unroll
        for (int nt = 0; nt < 8; nt++)
#pragma unroll
            for (int r = 0; r < 4; r++) acc[mt][nt][r] = 0.f;

    auto load_chunk = [&](int c, int st) {
        const int k0 = c * 32;
        __nv_bfloat16* base = gsm + st * 4 * GTILE;
#pragma unroll
        for (int w = 0; w < 2; w++) {
            int idx = tid + w * 256;
            int row = idx >> 2, seg = (idx & 3) * 8;
            uint32_t soff = (uint32_t)(row * SSTR + seg);
            CP16(smem_u32(base + 0 * GTILE + soff),
                 Ah + (size_t)(bm + row) * GK + k0 + seg);
            CP16(smem_u32(base + 1 * GTILE + soff),
                 Al + (size_t)(bm + row) * GK + k0 + seg);
            CP16(smem_u32(base + 2 * GTILE + soff),
                 Bt + (size_t)(bn + row) * (2 * GK) + k0 + seg);
            CP16(smem_u32(base + 3 * GTILE + soff),
                 Bt + (size_t)(bn + row) * (2 * GK) + GK + k0 + seg);
        }
        CP_COMMIT;
    };

    load_chunk(0, 0);

    int st = 0;
    for (int c = 0; c < NCHUNK; c++) {
        asm volatile("cp.async.wait_group 0;" ::: "memory");
        __syncthreads();
        if (c + 1 < NCHUNK) load_chunk(c + 1, st ^ 1);

        const __nv_bfloat16* base = gsm + st * 4 * GTILE;
        const uint32_t aHb = smem_u32(base + 0 * GTILE);
        const uint32_t aLb = smem_u32(base + 1 * GTILE);
        const uint32_t bHb = smem_u32(base + 2 * GTILE);
        const uint32_t bLb = smem_u32(base + 3 * GTILE);

#pragma unroll
        for (int ks = 0; ks < 32; ks += 16) {
            uint32_t ah[2][4], al[2][4], bh[8][2], bl[8][2];
            uint32_t aoff[2], boff[4];
#pragma unroll
            for (int mt = 0; mt < 2; mt++)
                aoff[mt] = (((wm + mt * 16 + (l & 15)) * SSTR) + ks + ((l >> 4) << 3)) * 2;
#pragma unroll
            for (int p = 0; p < 4; p++)
                boff[p] = (((wn + p * 16 + (l & 7) + ((l >> 4) << 3)) * SSTR) +
                           ks + (((l >> 3) & 1) << 3)) * 2;

#pragma unroll
            for (int mt = 0; mt < 2; mt++) LDSM_X4(ah[mt], aHb + aoff[mt]);
#pragma unroll
            for (int p = 0; p < 4; p++)
                asm volatile("ldmatrix.sync.aligned.m8n8.x4.shared.b16 {%0,%1,%2,%3}, [%4];"
                             : "=r"(bh[p * 2][0]), "=r"(bh[p * 2][1]),
                               "=r"(bh[p * 2 + 1][0]), "=r"(bh[p * 2 + 1][1])
                             : "r"(bHb + boff[p]));
#pragma unroll
            for (int mt = 0; mt < 2; mt++)
#pragma unroll
                for (int nt = 0; nt < 8; nt++) MMA16816(acc[mt][nt], ah[mt], bh[nt]);

#pragma unroll
            for (int p = 0; p < 4; p++)
                asm volatile("ldmatrix.sync.aligned.m8n8.x4.shared.b16 {%0,%1,%2,%3}, [%4];"
                             : "=r"(bl[p * 2][0]), "=r"(bl[p * 2][1]),
                               "=r"(bl[p * 2 + 1][0]), "=r"(bl[p * 2 + 1][1])
                             : "r"(bLb + boff[p]));
#pragma unroll
            for (int mt = 0; mt < 2; mt++)
#pragma unroll
                for (int nt = 0; nt < 8; nt++) MMA16816(acc[mt][nt], ah[mt], bl[nt]);

#pragma unroll
            for (int mt = 0; mt < 2; mt++) LDSM_X4(al[mt], aLb + aoff[mt]);
#pragma unroll
            for (int mt = 0; mt < 2; mt++)
#pragma unroll
                for (int nt = 0; nt < 8; nt++) MMA16816(acc[mt][nt], al[mt], bh[nt]);
        }
        st ^= 1;
    }

    if (Cf) {
#pragma unroll
        for (int mt = 0; mt < 2; mt++) {
            const int row = bm + wm + mt * 16 + (l >> 2);
#pragma unroll
            for (int nt = 0; nt < 8; nt++) {
                const int col = bn + wn + nt * 8 + (l & 3) * 2;
                *reinterpret_cast<float2*>(Cf + (size_t)row * Nc + col) =
                    make_float2(acc[mt][nt][0], acc[mt][nt][1]);
                *reinterpret_cast<float2*>(Cf + (size_t)(row + 8) * Nc + col) =
                    make_float2(acc[mt][nt][2], acc[mt][nt][3]);
            }
        }
    } else {
#pragma unroll
        for (int mt = 0; mt < 2; mt++) {
            const int row = bm + wm + mt * 16 + (l >> 2);
#pragma unroll
            for (int nt = 0; nt < 8; nt++) {
                const int col = bn + wn + nt * 8 + (l & 3) * 2;
                uint32_t h0, l0, h1, l1;
                split2(acc[mt][nt][0], acc[mt][nt][1], h0, l0);
                split2(acc[mt][nt][2], acc[mt][nt][3], h1, l1);
                *reinterpret_cast<uint32_t*>(Ch + (size_t)row * Nc + col)       = h0;
                *reinterpret_cast<uint32_t*>(Cl + (size_t)row * Nc + col)       = l0;
                *reinterpret_cast<uint32_t*>(Ch + (size_t)(row + 8) * Nc + col) = h1;
                *reinterpret_cast<uint32_t*>(Cl + (size_t)(row + 8) * Nc + col) = l1;
            }
        }
    }
}

// ---------------- tensor-core attention: 2 heads per block, Q hoisted pre-wait ----------------
#define ASTR 40
#define AT_TILE (Nn * ASTR)
#define MSTR 168
#define MAP_SM (Nn * MSTR)
#define ATTN_SMEM (MAP_SM * 4 + 2 * 4 * AT_TILE * 2)

__global__ __launch_bounds__(320, 1) void attn_mma(const __nv_bfloat16* __restrict__ qkvh,
                                                   const __nv_bfloat16* __restrict__ qkvl,
                                                   const float* __restrict__ mapsrc,
                                                   const float* __restrict__ bw,
                                                   const float* __restrict__ bb,
                                                   __nv_bfloat16* __restrict__ Ah,
                                                   __nv_bfloat16* __restrict__ Al) {
    extern __shared__ char asmem[];
    float* mapS = reinterpret_cast<float*>(asmem);
    __nv_bfloat16* tiles = reinterpret_cast<__nv_bfloat16*>(asmem + MAP_SM * 4);
    auto sKh = [&](int st) { return tiles + st * 4 * AT_TILE + 0 * AT_TILE; };
    auto sKl = [&](int st) { return tiles + st * 4 * AT_TILE + 1 * AT_TILE; };
    auto sVh = [&](int st) { return tiles + st * 4 * AT_TILE + 2 * AT_TILE; };
    auto sVl = [&](int st) { return tiles + st * 4 * AT_TILE + 3 * AT_TILE; };

    const int m = blockIdx.x, b = blockIdx.y;
    const int hbase = blockIdx.z * 2;
    const int tid = threadIdx.x, wid = tid >> 5, l = tid & 31;
    const size_t rowbase = ((size_t)b * Nn + m) * Nn;
    const float scale = 0.17677669529663687f;

    for (int idx = tid; idx < Nn * 40; idx += 320) {
        int row = idx / 40, c4 = idx % 40;
        CP16(smem_u32(mapS + row * MSTR + c4 * 4),
             mapsrc + (size_t)b * Nn * Nn + (size_t)row * Nn + c4 * 4);
    }
    CP_COMMIT;

    auto load_kv = [&](int h, int st) {
        for (int idx = tid; idx < Nn * 4; idx += 320) {
            int row = idx >> 2, seg = (idx & 3) * 8;
            size_t gro = (rowbase + row) * 768 + 256 + h * Dd;
            uint32_t so = (uint32_t)(row * ASTR + seg);
            CP16(smem_u32(sKh(st) + so), qkvh + gro + seg);
            CP16(smem_u32(sKl(st) + so), qkvl + gro + seg);
            CP16(smem_u32(sVh(st) + so), qkvh + gro + 256 + seg);
            CP16(smem_u32(sVl(st) + so), qkvl + gro + 256 + seg);
        }
        CP_COMMIT;
    };

    load_kv(hbase, 0);

    const int q0 = wid * 16;
    const int r0 = q0 + (l >> 2), r1 = r0 + 8;
    const int cpair = (l & 3) * 2;

    for (int e = 0; e < 2; e++) {
        const int h = hbase + e, st = e;

        // ---- Q a-frags straight from global, issued BEFORE the staging wait ----
        uint32_t qh[2][4], ql[2][4];
        {
            const size_t g0 = (rowbase + r0) * 768 + h * Dd;
            const size_t g1 = (rowbase + r1) * 768 + h * Dd;
#pragma unroll
            for (int kc = 0; kc < 2; kc++) {
                int col = kc * 16 + cpair;
                qh[kc][0] = *reinterpret_cast<const uint32_t*>(qkvh + g0 + col);
                qh[kc][1] = *reinterpret_cast<const uint32_t*>(qkvh + g1 + col);
                qh[kc][2] = *reinterpret_cast<const uint32_t*>(qkvh + g0 + col + 8);
                qh[kc][3] = *reinterpret_cast<const uint32_t*>(qkvh + g1 + col + 8);
                ql[kc][0] = *reinterpret_cast<const uint32_t*>(qkvl + g0 + col);
                ql[kc][1] = *reinterpret_cast<const uint32_t*>(qkvl + g1 + col);
                ql[kc][2] = *reinterpret_cast<const uint32_t*>(qkvl + g0 + col + 8);
                ql[kc][3] = *reinterpret_cast<const uint32_t*>(qkvl + g1 + col + 8);
            }
        }

        if (e == 0) {
            load_kv(hbase + 1, 1);
            asm volatile("cp.async.wait_group 1;" ::: "memory");
        } else {
            asm volatile("cp.async.wait_group 0;" ::: "memory");
        }
        __syncthreads();

        const float wv = bw[h], bv = bb[h];

        float S[20][4];
#pragma unroll
        for (int nt = 0; nt < 20; nt++)
#pragma unroll
            for (int r = 0; r < 4; r++) S[nt][r] = 0.f;

        const uint32_t kHb = smem_u32(sKh(st)), kLb = smem_u32(sKl(st));
#pragma unroll
        for (int nt = 0; nt < 20; nt++) {
#pragma unroll
            for (int kc = 0; kc < 2; kc++) {
                uint32_t off = (uint32_t)((nt * 8 + (l & 7)) * ASTR) * 2 +
                               (((l >> 3) & 1) << 4) + kc * 32;
                uint32_t bh[2], bl2[2];
                LDSM_X2(bh[0], bh[1], kHb + off);
                LDSM_X2(bl2[0], bl2[1], kLb + off);
                MMA16816(S[nt], qh[kc], bh);
                MMA16816(S[nt], qh[kc], bl2);
                MMA16816(S[nt], ql[kc], bh);
            }
        }

#pragma unroll
        for (int nt = 0; nt < 20; nt++) {
            int j0 = nt * 8 + cpair;
            S[nt][0] = S[nt][0] * scale + mapS[r0 * MSTR + j0]     * wv + bv;
            S[nt][1] = S[nt][1] * scale + mapS[r0 * MSTR + j0 + 1] * wv + bv;
            S[nt][2] = S[nt][2] * scale + mapS[r1 * MSTR + j0]     * wv + bv;
            S[nt][3] = S[nt][3] * scale + mapS[r1 * MSTR + j0 + 1] * wv + bv;
        }

        float m0 = -INFINITY, m1 = -INFINITY;
#pragma unroll
        for (int nt = 0; nt < 20; nt++) {
            m0 = fmaxf(m0, fmaxf(S[nt][0], S[nt][1]));
            m1 = fmaxf(m1, fmaxf(S[nt][2], S[nt][3]));
        }
        m0 = fmaxf(m0, __shfl_xor_sync(0xffffffffu, m0, 1));
        m0 = fmaxf(m0, __shfl_xor_sync(0xffffffffu, m0, 2));
        m1 = fmaxf(m1, __shfl_xor_sync(0xffffffffu, m1, 1));
        m1 = fmaxf(m1, __shfl_xor_sync(0xffffffffu, m1, 2));

        float l0 = 0.f, l1 = 0.f;
#pragma unroll
        for (int nt = 0; nt < 20; nt++) {
            S[nt][0] = __expf(S[nt][0] - m0); l0 += S[nt][0];
            S[nt][1] = __expf(S[nt][1] - m0); l0 += S[nt][1];
            S[nt][2] = __expf(S[nt][2] - m1); l1 += S[nt][2];
            S[nt][3] = __expf(S[nt][3] - m1); l1 += S[nt][3];
        }
        l0 += __shfl_xor_sync(0xffffffffu, l0, 1);
        l0 += __shfl_xor_sync(0xffffffffu, l0, 2);
        l1 += __shfl_xor_sync(0xffffffffu, l1, 1);
        l1 += __shfl_xor_sync(0xffffffffu, l1, 2);

        float O[4][4];
#pragma unroll
        for (int nt = 0; nt < 4; nt++)
#pragma unroll
            for (int r = 0; r < 4; r++) O[nt][r] = 0.f;

        const uint32_t vHb = smem_u32(sVh(st)), vLb = smem_u32(sVl(st));
#pragma unroll
        for (int kc = 0; kc < 10; kc++) {
            uint32_t aPh[4], aPl[4];
            split2(S[kc * 2][0],     S[kc * 2][1],     aPh[0], aPl[0]);
            split2(S[kc * 2][2],     S[kc * 2][3],     aPh[1], aPl[1]);
            split2(S[kc * 2 + 1][0], S[kc * 2 + 1][1], aPh[2], aPl[2]);
            split2(S[kc * 2 + 1][2], S[kc * 2 + 1][3], aPh[3], aPl[3]);

            uint32_t bvh[4][2], bvl[4][2];
#pragma unroll
            for (int dp = 0; dp < 2; dp++) {
                uint32_t off = (uint32_t)((kc * 16 + (l & 15)) * ASTR) * 2 +
                               ((l >> 4) << 4) + dp * 32;
                uint32_t rh[4], rl[4];
                LDSM_X4T(rh, vHb + off);
                LDSM_X4T(rl, vLb + off);
                bvh[dp * 2][0] = rh[0]; bvh[dp * 2][1] = rh[1];
                bvh[dp * 2 + 1][0] = rh[2]; bvh[dp * 2 + 1][1] = rh[3];
                bvl[dp * 2][0] = rl[0]; bvl[dp * 2][1] = rl[1];
                bvl[dp * 2 + 1][0] = rl[2]; bvl[dp * 2 + 1][1] = rl[3];
            }
#pragma unroll
            for (int nt = 0; nt < 4; nt++) {
                MMA16816(O[nt], aPh, bvh[nt]);
                MMA16816(O[nt], aPh, bvl[nt]);
                MMA16816(O[nt], aPl, bvh[nt]);
            }
        }

        const float inv0 = 1.f / l0, inv1 = 1.f / l1;
#pragma unroll
        for (int nt = 0; nt < 4; nt++) {
            int col = h * Dd + nt * 8 + cpair;
            uint32_t h0v, l0v, h1v, l1v;
            split2(O[nt][0] * inv0, O[nt][1] * inv0, h0v, l0v);
            split2(O[nt][2] * inv1, O[nt][3] * inv1, h1v, l1v);
            *reinterpret_cast<uint32_t*>(Ah + (rowbase + r0) * GK + col) = h0v;
            *reinterpret_cast<uint32_t*>(Al + (rowbase + r0) * GK + col) = l0v;
            *reinterpret_cast<uint32_t*>(Ah + (rowbase + r1) * GK + col) = h1v;
            *reinterpret_cast<uint32_t*>(Al + (rowbase + r1) * GK + col) = l1v;
        }
        if (e == 0) __syncthreads();
    }
}

// ---------------- Residual + LayerNorm: warp-per-row, no smem/syncs ----------------
__global__ __launch_bounds__(256) void ln_kernel(const float* __restrict__ xin,
                                                const float* __restrict__ proj,
                                                const float* __restrict__ g,
                                                const float* __restrict__ bt,
                                                float* __restrict__ out,
                                                __nv_bfloat16* __restrict__ Ah,
                                                __nv_bfloat16* __restrict__ Al) {
    const int wid = threadIdx.x >> 5, l = threadIdx.x & 31;
    const int r = blockIdx.x * 8 + wid;

    const float4* x4 = reinterpret_cast<const float4*>(xin + (size_t)r * Cc);
    const float4* p4 = reinterpret_cast<const float4*>(proj + (size_t)r * Cc);
    float4 v[2];
    float s = 0.f, s2 = 0.f;
#pragma unroll
    for (int k = 0; k < 2; k++) {
        float4 a = x4[l + k * 32], p = p4[l + k * 32];
        v[k] = make_float4(a.x + p.x, a.y + p.y, a.z + p.z, a.w + p.w);
        s  += v[k].x + v[k].y + v[k].z + v[k].w;
        s2 += v[k].x * v[k].x + v[k].y * v[k].y + v[k].z * v[k].z + v[k].w * v[k].w;
    }
#pragma unroll
    for (int o = 16; o > 0; o >>= 1) {
        s  += __shfl_xor_sync(0xffffffffu, s, o);
        s2 += __shfl_xor_sync(0xffffffffu, s2, o);
    }
    const float mean = s * (1.f / Cc);
    const float var  = s2 * (1.f / Cc) - mean * mean;
    const float rs   = rsqrtf(var + 1e-5f);

    const int bidx = r / (Nn * Nn);
    const int rem  = r % (Nn * Nn);
    const int mm   = rem / Nn;
    const int ii   = rem % Nn;
    const size_t rt = ((size_t)bidx * Nn + ii) * Nn + mm;

    const float4* g4 = reinterpret_cast<const float4*>(g);
    const float4* b4 = reinterpret_cast<const float4*>(bt);
    float4* o4 = reinterpret_cast<float4*>(out + rt * Cc);
#pragma unroll
    for (int k = 0; k < 2; k++) {
        float4 gg = g4[l + k * 32], bb2 = b4[l + k * 32];
        float4 y;
        y.x = (v[k].x - mean) * rs * gg.x + bb2.x;
        y.y = (v[k].y - mean) * rs * gg.y + bb2.y;
        y.z = (v[k].z - mean) * rs * gg.z + bb2.z;
        y.w = (v[k].w - mean) * rs * gg.w + bb2.w;
        o4[l + k * 32] = y;
        if (Ah) {
            uint32_t h0, l0, h1, l1;
            split2(y.x, y.y, h0, l0);
            split2(y.z, y.w, h1, l1);
            *reinterpret_cast<uint2*>(Ah + rt * GK + (l + k * 32) * 4) = make_uint2(h0, h1);
            *reinterpret_cast<uint2*>(Al + rt * GK + (l + k * 32) * 4) = make_uint2(l0, l1);
        }
    }
}

extern "C" void kernel_launch(void* const* d_in, const int* in_sizes, int n_in,
                              void* d_out, int out_size) {
    const float* pair      = (const float*)d_in[0];
    const float* bulk      = (const float*)d_in[1];
    const float* row_qkv_w = (const float*)d_in[2];
    const float* row_out_w = (const float*)d_in[3];
    const float* row_ln_g  = (const float*)d_in[4];
    const float* row_ln_b  = (const float*)d_in[5];
    const float* row_bw    = (const float*)d_in[6];
    const float* row_bb    = (const float*)d_in[7];
    const float* col_qkv_w = (const float*)d_in[8];
    const float* col_out_w = (const float*)d_in[9];
    const float* col_ln_g  = (const float*)d_in[10];
    const float* col_ln_b  = (const float*)d_in[11];
    const float* col_bw    = (const float*)d_in[12];
    const float* col_bb    = (const float*)d_in[13];
    float* out = (float*)d_out;

    float *proj, *x1, *mapT;
    __nv_bfloat16 *qkvh, *qkvl, *Ah, *Al, *Brq, *Bro, *Bcq, *Bco;
    cudaGetSymbolAddress((void**)&qkvh, g_qkvh);
    cudaGetSymbolAddress((void**)&qkvl, g_qkvl);
    cudaGetSymbolAddress((void**)&proj, g_proj);
    cudaGetSymbolAddress((void**)&x1,   g_x1);
    cudaGetSymbolAddress((void**)&mapT, g_mapT);
    cudaGetSymbolAddress((void**)&Ah,   g_Ah);
    cudaGetSymbolAddress((void**)&Al,   g_Al);
    cudaGetSymbolAddress((void**)&Brq,  g_Brq);
    cudaGetSymbolAddress((void**)&Bro,  g_Bro);
    cudaGetSymbolAddress((void**)&Bcq,  g_Bcq);
    cudaGetSymbolAddress((void**)&Bco,  g_Bco);

    cudaFuncSetAttribute(attn_mma, cudaFuncAttributeMaxDynamicSharedMemorySize, ATTN_SMEM);
    cudaFuncSetAttribute(gemm_mma, cudaFuncAttributeMaxDynamicSharedMemorySize, GSMEM);

    const int n4 = ROWS * GK / 4;
    const int gsplitA = (n4 + 255) / 256;
    const int nsplitW = 2 * GK * 768 + 2 * GK * 256;
    dim3 gq(768 / 128, ROWS / 128);
    dim3 gp(256 / 128, ROWS / 128);
    dim3 ga(Nn, Bb, Hh / 2);
    dim3 gt(Nn / 32, Nn / 32, Bb);

    // ---- prologue ----
    splitW<<<(nsplitW + 255) / 256, 256>>>(row_qkv_w, row_out_w, col_qkv_w, col_out_w,
                                           Brq, Bro, Bcq, Bco);
    tmap_kernel<<<gt, dim3(32, 8)>>>(bulk, mapT);
    splitA<<<gsplitA, 256>>>((const float4*)pair, Ah, Al, n4);

    // ---- pass 1 (row attention) ----
    gemm_mma<<<gq, 256, GSMEM>>>(Ah, Al, Brq, nullptr, qkvh, qkvl, 768);
    attn_mma<<<ga, 320, ATTN_SMEM>>>(qkvh, qkvl, bulk, row_bw, row_bb, Ah, Al);
    gemm_mma<<<gp, 256, GSMEM>>>(Ah, Al, Bro, proj, nullptr, nullptr, 256);
    ln_kernel<<<ROWS / 8, 256>>>(pair, proj, row_ln_g, row_ln_b, x1, Ah, Al);

    // ---- pass 2 (column attention) ----
    gemm_mma<<<gq, 256, GSMEM>>>(Ah, Al, Bcq, nullptr, qkvh, qkvl, 768);
    attn_mma<<<ga, 320, ATTN_SMEM>>>(qkvh, qkvl, mapT, col_bw, col_bb, Ah, Al);
    gemm_mma<<<gp, 256, GSMEM>>>(Ah, Al, Bco, proj, nullptr, nullptr, 256);
    ln_kernel<<<ROWS / 8, 256>>>(x1, proj, col_ln_g, col_ln_b, out, nullptr, nullptr);
}